// round 16
// baseline (speedup 1.0000x reference)
#include <cuda_runtime.h>
#include <cstdint>

// ---------------- configuration ----------------
#define THREADS   512
#define NWARP     (THREADS / 32)        // 16
#define IPT       4                     // items per thread
#define TILE      (THREADS * IPT)       // 2048 elements per block
#define NEXP      64
#define MAXB      296
#define NSLOT     (IPT * NWARP)         // 64 (round,warp) slots
#define NCHUNK    16                    // chunks; NSLOT/NCHUNK = 4 slots each
#define NGRP      (THREADS / NEXP)      // 8 partial groups in Phase C

// ---------------- scratch (static device globals) ----------------
__device__ unsigned int g_blockHist[MAXB * NEXP];   // block-major [b][e]
__device__ unsigned int g_count = 0;
__device__ unsigned int g_gen   = 0;

// sense-reversing grid barrier; resets g_count each use -> graph-replay safe
__device__ __forceinline__ void grid_barrier(int nblocks) {
    __syncthreads();
    if (threadIdx.x == 0) {
        __threadfence();
        unsigned gen = *((volatile unsigned int*)&g_gen);
        if (atomicAdd(&g_count, 1u) == (unsigned)(nblocks - 1)) {
            g_count = 0u;
            __threadfence();
            *((volatile unsigned int*)&g_gen) = gen + 1u;
        } else {
            while (*((volatile unsigned int*)&g_gen) == gen) __nanosleep(64);
            __threadfence();
        }
    }
    __syncthreads();
}

// inclusive warp scan (32 lanes)
__device__ __forceinline__ unsigned int wscan(unsigned int v) {
    int lane = threadIdx.x & 31;
#pragma unroll
    for (int d = 1; d < 32; d <<= 1) {
        unsigned int n = __shfl_up_sync(0xFFFFFFFFu, v, d);
        if (lane >= d) v += n;
    }
    return v;
}

__global__ void __launch_bounds__(THREADS, 2)
fused_kernel(const float* __restrict__ scores,
             const int*   __restrict__ experts,
             const int*   __restrict__ topk_ptr,
             float* __restrict__ out_scores,
             float* __restrict__ out_tok,
             float* __restrict__ out_counts,
             int total, int B) {
    __shared__ uint16_t           cnt16 [NSLOT * NEXP];   // 8 KB
    __shared__ uint16_t           sums16[NCHUNK * NEXP];  // 2 KB
    __shared__ unsigned long long s_pk  [TILE];           // 16 KB packed
    __shared__ unsigned int       ptot  [NGRP * NEXP];    // 2 KB
    __shared__ unsigned int       ppre  [NGRP * NEXP];    // 2 KB
    __shared__ unsigned int       ebl   [NEXP];           // block-local base
    __shared__ unsigned int       adj   [NEXP];           // glob - local base

    const int t    = threadIdx.x;
    const int lane = t & 31;
    const int wid  = t >> 5;
    const int b    = blockIdx.x;

    const int topk  = *topk_ptr;
    const bool pow2 = (topk & (topk - 1)) == 0;
    const int shift = pow2 ? (31 - __clz(topk)) : 0;

    // zero count matrix (u32-wide)
#pragma unroll
    for (int i = t; i < NSLOT * NEXP / 2; i += THREADS)
        ((unsigned int*)cnt16)[i] = 0u;
    __syncthreads();

    // ---------------- Phase A: load, warp ranks, count matrix -------------
    const int base = b * TILE;
    int   e[IPT];
    int   rk[IPT];
    float sc[IPT];

#pragma unroll
    for (int r = 0; r < IPT; r++) {
        int idx = base + r * THREADS + t;            // striped = flat order
        bool ok = idx < total;
        e[r]  = ok ? experts[idx] : -1;
        sc[r] = ok ? scores[idx] : 0.0f;
        unsigned int mask = __match_any_sync(0xFFFFFFFFu, e[r]);
        rk[r] = __popc(mask & ((1u << lane) - 1u));
        if (lane == (__ffs(mask) - 1) && (unsigned)e[r] < NEXP)
            cnt16[(r * NWARP + wid) * NEXP + e[r]] = (uint16_t)__popc(mask);
    }
    __syncthreads();

    // chunk sums over slots per expert; 8 groups cover 16 chunks
    {
        int ee = t & 63;
#pragma unroll
        for (int cc = t >> 6; cc < NCHUNK; cc += NGRP) {
            unsigned int s = 0;
#pragma unroll
            for (int i = 0; i < NSLOT / NCHUNK; i++)
                s += cnt16[(cc * (NSLOT / NCHUNK) + i) * NEXP + ee];
            sums16[cc * NEXP + ee] = (uint16_t)s;
        }
    }
    __syncthreads();

    // warp 0 only: per-expert chunk scan -> block hist; expert-base scan.
    // lane L owns experts L and L+32; no cross-warp traffic -> no extra syncs
    if (wid == 0) {
        unsigned int tot0 = 0, tot1 = 0;
#pragma unroll
        for (int c = 0; c < NCHUNK; c++) {
            unsigned int v = sums16[c * NEXP + lane];
            sums16[c * NEXP + lane] = (uint16_t)tot0;
            tot0 += v;
        }
#pragma unroll
        for (int c = 0; c < NCHUNK; c++) {
            unsigned int v = sums16[c * NEXP + lane + 32];
            sums16[c * NEXP + lane + 32] = (uint16_t)tot1;
            tot1 += v;
        }
        g_blockHist[b * NEXP + lane]      = tot0;
        g_blockHist[b * NEXP + lane + 32] = tot1;
        unsigned int i0 = wscan(tot0);
        unsigned int all0 = __shfl_sync(0xFFFFFFFFu, i0, 31);
        unsigned int i1 = wscan(tot1);
        ebl[lane]      = i0 - tot0;
        ebl[lane + 32] = all0 + i1 - tot1;
    }
    __syncthreads();

    // rewrite cnt16 with within-expert prefix + block-local expert base
    {
        int ee = t & 63;
        unsigned int eb = ebl[ee];
#pragma unroll
        for (int cc = t >> 6; cc < NCHUNK; cc += NGRP) {
            unsigned int run = (unsigned int)sums16[cc * NEXP + ee] + eb;
#pragma unroll
            for (int i = 0; i < NSLOT / NCHUNK; i++) {
                int k = cc * (NSLOT / NCHUNK) + i;
                unsigned int v = cnt16[k * NEXP + ee];
                cnt16[k * NEXP + ee] = (uint16_t)run;
                run += v;
            }
        }
    }
    __syncthreads();

    // placement: single packed STS.64 of (score, expert, token)
#pragma unroll
    for (int r = 0; r < IPT; r++) {
        if ((unsigned)e[r] < NEXP) {
            int idx = base + r * THREADS + t;
            int tok = pow2 ? (idx >> shift) : (idx / topk);
            unsigned int pl = (unsigned int)cnt16[(r * NWARP + wid) * NEXP + e[r]]
                            + (unsigned int)rk[r];
            unsigned int lo = ((unsigned int)e[r] << 16) | (unsigned int)tok;
            s_pk[pl] = ((unsigned long long)__float_as_uint(sc[r]) << 32) | lo;
        }
    }

    grid_barrier(B);

    // ---------------- Phase C: coalesced partials over block-major hist ---
    {
        int g = t >> 6, ee = t & 63;
        unsigned int tot = 0, pre = 0;
        for (int b2 = g; b2 < B; b2 += NGRP) {
            unsigned int v = g_blockHist[b2 * NEXP + ee];
            tot += v;
            if (b2 < b) pre += v;
        }
        ptot[g * NEXP + ee] = tot;
        ppre[g * NEXP + ee] = pre;
    }
    __syncthreads();

    // warp 0: combine partials, expert-base scan, adj = glob - local
    if (wid == 0) {
        unsigned int tv0 = 0, pv0 = 0, tv1 = 0, pv1 = 0;
#pragma unroll
        for (int g = 0; g < NGRP; g++) {
            tv0 += ptot[g * NEXP + lane];
            pv0 += ppre[g * NEXP + lane];
            tv1 += ptot[g * NEXP + lane + 32];
            pv1 += ppre[g * NEXP + lane + 32];
        }
        unsigned int i0 = wscan(tv0);
        unsigned int all0 = __shfl_sync(0xFFFFFFFFu, i0, 31);
        unsigned int i1 = wscan(tv1);
        adj[lane]      = (i0 - tv0) + pv0 - ebl[lane];
        adj[lane + 32] = (all0 + i1 - tv1) + pv1 - ebl[lane + 32];
        if (b == 0) {
            out_counts[lane]      = (float)tv0;
            out_counts[lane + 32] = (float)tv1;
        }
    }
    __syncthreads();

    // ---------------- write-out: LDS.64 + 2 coalesced STG -----------------
    const int valid = min(TILE, total - base);
#pragma unroll
    for (int r = 0; r < IPT; r++) {
        int j = r * THREADS + t;                     // sorted position
        if (j < valid) {
            unsigned long long pk = s_pk[j];
            unsigned int lo = (unsigned int)pk;
            unsigned int dst = adj[lo >> 16] + (unsigned int)j;
            out_scores[dst] = __uint_as_float((unsigned int)(pk >> 32));
            out_tok[dst]    = (float)(lo & 0xFFFFu);
        }
    }
}

// ---------------- launch ----------------
extern "C" void kernel_launch(void* const* d_in, const int* in_sizes, int n_in,
                              void* d_out, int out_size) {
    const float* scores   = (const float*)d_in[0];
    const int*   experts  = (const int*)  d_in[1];
    const int*   topk_ptr = (const int*)  d_in[3];

    int total = in_sizes[0];                        // 524288
    int B = (total + TILE - 1) / TILE;              // 256
    if (B > MAXB) B = MAXB;                         // all blocks co-resident

    float* out        = (float*)d_out;
    float* out_scores = out;                        // [0, total)
    float* out_tok    = out + total;                // [total, 2*total)
    float* out_counts = out + 2 * (size_t)total;    // [2*total, +64)

    fused_kernel<<<B, THREADS>>>(scores, experts, topk_ptr,
                                 out_scores, out_tok, out_counts,
                                 total, B);
}

// round 17
// speedup vs baseline: 1.0043x; 1.0043x over previous
#include <cuda_runtime.h>
#include <cstdint>

// ---------------- configuration ----------------
#define THREADS   1024
#define NWARP     (THREADS / 32)        // 32
#define IPT       4                     // items per thread
#define TILE      (THREADS * IPT)       // 4096 elements per block
#define NEXP      64
#define MAXB      148                   // 1 block/SM, all co-resident
#define NSLOT     (IPT * NWARP)         // 128 (round,warp) slots
#define NCHUNK    16                    // chunks of 8 slots
#define NGRP      (THREADS / NEXP)      // 16 groups (one chunk each)

// ---------------- scratch (static device globals) ----------------
__device__ unsigned int g_blockHist[MAXB * NEXP];   // block-major [b][e]
__device__ unsigned int g_count = 0;
__device__ unsigned int g_gen   = 0;

// sense-reversing grid barrier, plain volatile poll (NO nanosleep:
// nanosleep quantization adds its quantum to every block's tail)
__device__ __forceinline__ void grid_barrier(int nblocks) {
    __syncthreads();
    if (threadIdx.x == 0) {
        __threadfence();
        unsigned gen = *((volatile unsigned int*)&g_gen);
        if (atomicAdd(&g_count, 1u) == (unsigned)(nblocks - 1)) {
            g_count = 0u;
            __threadfence();
            *((volatile unsigned int*)&g_gen) = gen + 1u;
        } else {
            while (*((volatile unsigned int*)&g_gen) == gen) { }
            __threadfence();
        }
    }
    __syncthreads();
}

// inclusive warp scan
__device__ __forceinline__ unsigned int wscan(unsigned int v) {
    int lane = threadIdx.x & 31;
#pragma unroll
    for (int d = 1; d < 32; d <<= 1) {
        unsigned int n = __shfl_up_sync(0xFFFFFFFFu, v, d);
        if (lane >= d) v += n;
    }
    return v;
}

__global__ void __launch_bounds__(THREADS, 1)
fused_kernel(const float* __restrict__ scores,
             const int*   __restrict__ experts,
             const int*   __restrict__ topk_ptr,
             float* __restrict__ out_scores,
             float* __restrict__ out_tok,
             float* __restrict__ out_counts,
             int total, int B) {
    __shared__ uint16_t           cnt16 [NSLOT * NEXP];   // 16 KB
    __shared__ uint16_t           sums16[NCHUNK * NEXP];  // 2 KB
    __shared__ unsigned long long s_pk  [TILE];           // 32 KB packed
    __shared__ unsigned int       ptot  [NGRP * NEXP];    // 4 KB
    __shared__ unsigned int       ppre  [NGRP * NEXP];    // 4 KB
    __shared__ unsigned int       ebl   [NEXP];
    __shared__ unsigned int       adj   [NEXP];

    const int t    = threadIdx.x;
    const int lane = t & 31;
    const int wid  = t >> 5;
    const int b    = blockIdx.x;

    const int topk  = *topk_ptr;
    const bool pow2 = (topk & (topk - 1)) == 0;
    const int shift = pow2 ? (31 - __clz(topk)) : 0;

    // zero count matrix (u32-wide)
#pragma unroll
    for (int i = t; i < NSLOT * NEXP / 2; i += THREADS)
        ((unsigned int*)cnt16)[i] = 0u;
    __syncthreads();

    // ---------------- Phase A: load, warp ranks, count matrix -------------
    const int base = b * TILE;
    int   e[IPT];
    int   rk[IPT];
    float sc[IPT];

#pragma unroll
    for (int r = 0; r < IPT; r++) {
        int idx = base + r * THREADS + t;            // striped = flat order
        bool ok = idx < total;
        e[r]  = ok ? __ldcs(&experts[idx]) : -1;
        sc[r] = ok ? __ldcs(&scores[idx]) : 0.0f;
        unsigned int mask = __match_any_sync(0xFFFFFFFFu, e[r]);
        rk[r] = __popc(mask & ((1u << lane) - 1u));
        if (lane == (__ffs(mask) - 1) && (unsigned)e[r] < NEXP)
            cnt16[(r * NWARP + wid) * NEXP + e[r]] = (uint16_t)__popc(mask);
    }
    __syncthreads();

    // chunk sums: group g (= t>>6) handles chunk g; single pass, no loop
    {
        int g = t >> 6, ee = t & 63;
        unsigned int s = 0;
#pragma unroll
        for (int i = 0; i < NSLOT / NCHUNK; i++)
            s += cnt16[(g * (NSLOT / NCHUNK) + i) * NEXP + ee];
        sums16[g * NEXP + ee] = (uint16_t)s;
    }
    __syncthreads();

    // warp 0: per-expert chunk scan -> block hist; expert-base scan
    if (wid == 0) {
        unsigned int tot0 = 0, tot1 = 0;
#pragma unroll
        for (int c = 0; c < NCHUNK; c++) {
            unsigned int v = sums16[c * NEXP + lane];
            sums16[c * NEXP + lane] = (uint16_t)tot0;
            tot0 += v;
        }
#pragma unroll
        for (int c = 0; c < NCHUNK; c++) {
            unsigned int v = sums16[c * NEXP + lane + 32];
            sums16[c * NEXP + lane + 32] = (uint16_t)tot1;
            tot1 += v;
        }
        g_blockHist[b * NEXP + lane]      = tot0;
        g_blockHist[b * NEXP + lane + 32] = tot1;
        unsigned int i0 = wscan(tot0);
        unsigned int all0 = __shfl_sync(0xFFFFFFFFu, i0, 31);
        unsigned int i1 = wscan(tot1);
        ebl[lane]      = i0 - tot0;
        ebl[lane + 32] = all0 + i1 - tot1;
    }
    __syncthreads();

    // rewrite cnt16 with within-expert prefix + block-local expert base
    {
        int g = t >> 6, ee = t & 63;
        unsigned int run = (unsigned int)sums16[g * NEXP + ee] + ebl[ee];
#pragma unroll
        for (int i = 0; i < NSLOT / NCHUNK; i++) {
            int k = g * (NSLOT / NCHUNK) + i;
            unsigned int v = cnt16[k * NEXP + ee];
            cnt16[k * NEXP + ee] = (uint16_t)run;
            run += v;
        }
    }
    __syncthreads();

    // placement: one packed STS.64 (score | expert<<16 | token)
#pragma unroll
    for (int r = 0; r < IPT; r++) {
        if ((unsigned)e[r] < NEXP) {
            int idx = base + r * THREADS + t;
            int tok = pow2 ? (idx >> shift) : (idx / topk);
            unsigned int pl = (unsigned int)cnt16[(r * NWARP + wid) * NEXP + e[r]]
                            + (unsigned int)rk[r];
            unsigned int lo = ((unsigned int)e[r] << 16) | (unsigned int)tok;
            s_pk[pl] = ((unsigned long long)__float_as_uint(sc[r]) << 32) | lo;
        }
    }

    grid_barrier(B);

    // ---------------- Phase C: coalesced partials over block-major hist ---
    {
        int g = t >> 6, ee = t & 63;
        unsigned int tot = 0, pre = 0;
        for (int b2 = g; b2 < B; b2 += NGRP) {
            unsigned int v = g_blockHist[b2 * NEXP + ee];
            tot += v;
            if (b2 < b) pre += v;
        }
        ptot[g * NEXP + ee] = tot;
        ppre[g * NEXP + ee] = pre;
    }
    __syncthreads();

    // warp 0: combine partials, global expert-base scan, adj = glob - local
    if (wid == 0) {
        unsigned int tv0 = 0, pv0 = 0, tv1 = 0, pv1 = 0;
#pragma unroll
        for (int g = 0; g < NGRP; g++) {
            tv0 += ptot[g * NEXP + lane];
            pv0 += ppre[g * NEXP + lane];
            tv1 += ptot[g * NEXP + lane + 32];
            pv1 += ppre[g * NEXP + lane + 32];
        }
        unsigned int i0 = wscan(tv0);
        unsigned int all0 = __shfl_sync(0xFFFFFFFFu, i0, 31);
        unsigned int i1 = wscan(tv1);
        adj[lane]      = (i0 - tv0) + pv0 - ebl[lane];
        adj[lane + 32] = (all0 + i1 - tv1) + pv1 - ebl[lane + 32];
        if (b == 0) {
            out_counts[lane]      = (float)tv0;
            out_counts[lane + 32] = (float)tv1;
        }
    }
    __syncthreads();

    // ---------------- write-out: LDS.64 + 2 streaming coalesced STG -------
    const int valid = min(TILE, total - base);
#pragma unroll
    for (int r = 0; r < IPT; r++) {
        int j = r * THREADS + t;                     // sorted position
        if (j < valid) {
            unsigned long long pk = s_pk[j];
            unsigned int lo = (unsigned int)pk;
            unsigned int dst = adj[lo >> 16] + (unsigned int)j;
            __stcs(&out_scores[dst], __uint_as_float((unsigned int)(pk >> 32)));
            __stcs(&out_tok[dst], (float)(lo & 0xFFFFu));
        }
    }
}

// ---------------- launch ----------------
extern "C" void kernel_launch(void* const* d_in, const int* in_sizes, int n_in,
                              void* d_out, int out_size) {
    const float* scores   = (const float*)d_in[0];
    const int*   experts  = (const int*)  d_in[1];
    const int*   topk_ptr = (const int*)  d_in[3];

    int total = in_sizes[0];                        // 524288
    int B = (total + TILE - 1) / TILE;              // 128
    if (B > MAXB) B = MAXB;                         // 1 block/SM, co-resident

    float* out        = (float*)d_out;
    float* out_scores = out;                        // [0, total)
    float* out_tok    = out + total;                // [total, 2*total)
    float* out_counts = out + 2 * (size_t)total;    // [2*total, +64)

    fused_kernel<<<B, THREADS>>>(scores, experts, topk_ptr,
                                 out_scores, out_tok, out_counts,
                                 total, B);
}